// round 15
// baseline (speedup 1.0000x reference)
#include <cuda_runtime.h>
#include <cuda_fp16.h>
#include <math.h>
#include <stdint.h>

#define N_TOK 16384
#define C_DIM 768
#define I_DIM 1536
#define E_EXP 16
#define E_ALL 17
#define SLOTS (3*N_TOK)
#define TILE_B 16384
#define STAGE_F (3*TILE_B)
#define STAGE_D (2*TILE_B)
#define SMEM_F (3*STAGE_F + 1024)
#define SMEM_D (3*STAGE_D + 1024)

// ---------------- static device scratch ----------------
__device__ int   g_counts[E_EXP];
__device__ int   g_offsets[E_EXP];
__device__ int   g_cursor[E_EXP];
__device__ int   g_re[N_TOK*2];
__device__ float g_rw[N_TOK*2];
__device__ int   g_ids[SLOTS];
__device__ float g_wt[SLOTS];
__device__ int   g_slot_of[N_TOK*2];

__device__ __half g_xh[(size_t)N_TOK*C_DIM];          // x single fp16 plane
__device__ __half g_wg[(size_t)E_ALL*I_DIM*C_DIM];    // [(e*I+n)*C+k]
__device__ __half g_wu[(size_t)E_ALL*I_DIM*C_DIM];
__device__ __half g_wd[(size_t)E_ALL*C_DIM*I_DIM];    // [(e*C+n)*I+k]
__device__ __half g_hh[(size_t)SLOTS*I_DIM];          // H single fp16 plane
__device__ float g_O[(size_t)SLOTS*C_DIM];

// ---------------- PTX helpers (base ISA only) ----------------
__device__ __forceinline__ uint32_t smem_u32(const void* p){
    uint32_t a;
    asm("{ .reg .u64 t; cvta.to.shared.u64 t, %1; cvt.u32.u64 %0, t; }" : "=r"(a) : "l"(p));
    return a;
}
__device__ __forceinline__ void cp_row(uint32_t sbase, const void* src, int t){
    #pragma unroll
    for (int ch = 0; ch < 8; ch++){
        uint32_t off = (uint32_t)t*128u + (uint32_t)ch*16u;
        uint32_t dst = sbase + (off ^ ((off >> 3) & 0x70u));
        asm volatile("cp.async.cg.shared.global [%0], [%1], 16;"
            :: "r"(dst), "l"((const char*)src + ch*16) : "memory");
    }
}
__device__ __forceinline__ void cp_commit(){ asm volatile("cp.async.commit_group;" ::: "memory"); }
__device__ __forceinline__ void cp_wait1(){ asm volatile("cp.async.wait_group 1;" ::: "memory"); }
__device__ __forceinline__ void cp_wait0(){ asm volatile("cp.async.wait_group 0;" ::: "memory"); }

__device__ __forceinline__ void ldsm4(uint32_t* r, uint32_t addr){
    asm volatile("ldmatrix.sync.aligned.m8n8.x4.shared.b16 {%0,%1,%2,%3}, [%4];"
        : "=r"(r[0]), "=r"(r[1]), "=r"(r[2]), "=r"(r[3]) : "r"(addr));
}
__device__ __forceinline__ void hmma(float* d, const uint32_t* a, const uint32_t* b){
    asm volatile("mma.sync.aligned.m16n8k16.row.col.f32.f16.f16.f32 "
        "{%0,%1,%2,%3}, {%4,%5,%6,%7}, {%8,%9}, {%0,%1,%2,%3};"
        : "+f"(d[0]), "+f"(d[1]), "+f"(d[2]), "+f"(d[3])
        : "r"(a[0]), "r"(a[1]), "r"(a[2]), "r"(a[3]), "r"(b[0]), "r"(b[1]));
}

// ---------------- routing setup ----------------
// router: per-token top2 (no global atomics; counting moved to scan2)
__global__ void router_kernel(const float* __restrict__ x, const float* __restrict__ wgate,
                              const float* __restrict__ bias){
    int warp = (blockIdx.x * blockDim.x + threadIdx.x) >> 5;
    int lane = threadIdx.x & 31;
    if (warp >= N_TOK) return;
    float acc = 0.f;
    if (lane < E_EXP){
        const float* xr = x + (size_t)warp * C_DIM;
        #pragma unroll 8
        for (int c = 0; c < C_DIM; c++) acc = fmaf(xr[c], wgate[c*E_EXP + lane], acc);
        acc += bias[lane];
    }
    float l0 = -1e30f, l1 = -1e30f; int i0 = 0, i1 = 0;
    #pragma unroll
    for (int e = 0; e < E_EXP; e++){
        float v = __shfl_sync(0xffffffffu, acc, e);
        if (v > l0)      { l1 = l0; i1 = i0; l0 = v; i0 = e; }
        else if (v > l1) { l1 = v;  i1 = e; }
    }
    if (lane == 0){
        float w0 = 1.f / (1.f + __expf(l1 - l0));
        g_re[warp*2+0] = i0; g_rw[warp*2+0] = w0;
        g_re[warp*2+1] = i1; g_rw[warp*2+1] = 1.f - w0;
    }
}

// scan2: zero + count + exclusive scan in one 1-block kernel
__global__ void scan2_kernel(){
    __shared__ int cnt[E_EXP];
    if (threadIdx.x < E_EXP) cnt[threadIdx.x] = 0;
    __syncthreads();
    for (int i = threadIdx.x; i < N_TOK*2; i += blockDim.x)
        atomicAdd(&cnt[g_re[i]], 1);
    __syncthreads();
    if (threadIdx.x == 0){
        int off = 0;
        for (int e = 0; e < E_EXP; e++){
            g_counts[e] = cnt[e]; g_offsets[e] = off; g_cursor[e] = off; off += cnt[e];
        }
    }
}

__global__ void fill_kernel(){
    int t = blockIdx.x * blockDim.x + threadIdx.x;
    if (t >= N_TOK) return;
    #pragma unroll
    for (int s = 0; s < 2; s++){
        int e = g_re[t*2+s];
        int pos = atomicAdd(&g_cursor[e], 1);
        g_ids[pos] = t; g_wt[pos] = g_rw[t*2+s]; g_slot_of[t*2+s] = pos;
    }
    g_ids[2*N_TOK + t] = t; g_wt[2*N_TOK + t] = 1.f;
}

// ---------------- conversions ----------------
__global__ void conv_x_kernel(const float* __restrict__ x){
    size_t i = (size_t)blockIdx.x * blockDim.x + threadIdx.x;
    if (i >= (size_t)N_TOK*C_DIM) return;
    g_xh[i] = __float2half(x[i]);
}

// all six weight conversions in ONE launch. z = type*E_ALL + e; output arrays
// selected DEVICE-SIDE (never pass __device__ symbols as host-side args).
__global__ void convT_all_kernel(const float* __restrict__ wg, const float* __restrict__ swg,
                                 const float* __restrict__ wu, const float* __restrict__ swu,
                                 const float* __restrict__ wd, const float* __restrict__ swd){
    __shared__ float t[32][33];
    int z = blockIdx.z;
    int type = z / E_ALL;          // 0=wg 1=wu 2=wd
    int e = z % E_ALL;             // 0..16 (16 = shared)
    int K, N;
    const float* W;
    __half* outp;
    if (type == 0){ K = C_DIM; N = I_DIM; outp = g_wg;
        W = (e < E_EXP) ? wg + (size_t)e*K*N : swg; }
    else if (type == 1){ K = C_DIM; N = I_DIM; outp = g_wu;
        W = (e < E_EXP) ? wu + (size_t)e*K*N : swu; }
    else { K = I_DIM; N = C_DIM; outp = g_wd;
        W = (e < E_EXP) ? wd + (size_t)e*K*N : swd; }
    int n0, k0;
    if (type < 2){ n0 = blockIdx.x*32; k0 = blockIdx.y*32; }   // N=1536(48), K=768(24)
    else         { k0 = blockIdx.x*32; n0 = blockIdx.y*32; }   // K=1536(48), N=768(24)
    int tx = threadIdx.x, ty = threadIdx.y;   // (32,8)
    #pragma unroll
    for (int i = 0; i < 4; i++)
        t[ty + i*8][tx] = W[(size_t)(k0 + ty + i*8)*N + n0 + tx];
    __syncthreads();
    #pragma unroll
    for (int i = 0; i < 4; i++){
        int n = n0 + ty + i*8;
        size_t o = ((size_t)e*N + n)*K + k0 + tx;
        outp[o] = __float2half(t[tx][ty + i*8]);
    }
}

// ---------------- fused gate+up fp16 kernel (single product, 3-stage) ----------------
// CTA 128x128, 512 thr (16 warps, 4x4, warp tile 32x32), K-chunk 64 halfs (128B).
// Stage tiles: A@0 G@16K U@32K. One __syncthreads per kt; loads issued pre-compute.
__global__ void __launch_bounds__(512) fused_gateup_kernel(){
    int z = blockIdx.z, cnt, base;
    if (z == E_EXP){ cnt = N_TOK; base = 2*N_TOK; }
    else           { cnt = g_counts[z]; base = g_offsets[z]; }
    int rb = blockIdx.y;
    if (rb*128 >= cnt) return;
    int n0 = blockIdx.x * 128;

    extern __shared__ char smem[];
    uint32_t sb = (smem_u32(smem) + 1023u) & ~1023u;
    int tid = threadIdx.x, lane = tid & 31, wid = tid >> 5;
    int warp_m = wid >> 2, warp_n = wid & 3;

    // loader: 3 tiles x 128 rows = 384 rows; threads 384..511 idle
    int ltile = tid >> 7, lrow = tid & 127;
    bool lval = tid < 384;
    const char* lsrc = (const char*)g_xh;
    if (lval){
        if (ltile == 0){
            int r = rb*128 + lrow; int rr = r < cnt ? r : cnt - 1;
            int tok = g_ids[base + rr];
            lsrc = (const char*)(g_xh + (size_t)tok*C_DIM);
        } else {
            size_t wr = ((size_t)z*I_DIM + n0 + lrow)*C_DIM;
            lsrc = (const char*)((ltile == 1 ? g_wg : g_wu) + wr);
        }
    }
    uint32_t ltoff = (uint32_t)ltile*TILE_B;
    auto load_stage = [&](int s, int kt){
        uint32_t st = sb + (uint32_t)s*STAGE_F;
        if (lval) cp_row(st + ltoff, lsrc + kt*128, lrow);
        cp_commit();
    };

    int mat = lane >> 3;
    uint32_t xm = (uint32_t)(lane & 7) << 4;
    uint32_t rA[2], rB[2];
    #pragma unroll
    for (int mt = 0; mt < 2; mt++)
        rA[mt] = (uint32_t)(warp_m*32 + mt*16 + (mat & 1)*8 + (lane & 7)) << 7;
    #pragma unroll
    for (int p = 0; p < 2; p++)
        rB[p] = (uint32_t)(warp_n*32 + p*16 + ((mat >> 1) & 1)*8 + (lane & 7)) << 7;
    uint32_t caK = (uint32_t)((mat >> 1) & 1) * 16;
    uint32_t cbK = (uint32_t)(mat & 1) * 16;

    float ag[2][4][4], au[2][4][4];
    #pragma unroll
    for (int a = 0; a < 2; a++)
        #pragma unroll
        for (int b = 0; b < 4; b++)
            #pragma unroll
            for (int c = 0; c < 4; c++){ ag[a][b][c] = 0.f; au[a][b][c] = 0.f; }

    const int KT = C_DIM/64;   // 12
    load_stage(0, 0);
    load_stage(1, 1);

    for (int kt = 0; kt < KT; kt++){
        if (kt + 1 < KT) cp_wait1(); else cp_wait0();
        __syncthreads();
        if (kt + 2 < KT) load_stage((kt + 2) % 3, kt + 2);   // overlaps compute
        uint32_t st = sb + (uint32_t)(kt % 3)*STAGE_F;
        uint32_t At = st, Gt = st + TILE_B, Ut = st + 2*TILE_B;
        #pragma unroll
        for (int ks = 0; ks < 4; ks++){
            uint32_t cA = ((uint32_t)ks*32 + caK) ^ xm;
            uint32_t cB = ((uint32_t)ks*32 + cbK) ^ xm;
            uint32_t ah[2][4];
            ldsm4(ah[0], At + rA[0] + cA); ldsm4(ah[1], At + rA[1] + cA);
            uint32_t bg[2][4], bu[2][4];
            ldsm4(bg[0], Gt + rB[0] + cB); ldsm4(bg[1], Gt + rB[1] + cB);
            ldsm4(bu[0], Ut + rB[0] + cB); ldsm4(bu[1], Ut + rB[1] + cB);
            #pragma unroll
            for (int mt = 0; mt < 2; mt++)
                #pragma unroll
                for (int nt = 0; nt < 4; nt++)
                    hmma(ag[mt][nt], ah[mt], &bg[nt>>1][(nt&1)*2]);
            #pragma unroll
            for (int mt = 0; mt < 2; mt++)
                #pragma unroll
                for (int nt = 0; nt < 4; nt++)
                    hmma(au[mt][nt], ah[mt], &bu[nt>>1][(nt&1)*2]);
        }
    }

    // epilogue: h = silu(g)*u -> single fp16 plane
    int qr = lane >> 2, qc = (lane & 3)*2;
    #pragma unroll
    for (int mt = 0; mt < 2; mt++)
        #pragma unroll
        for (int h2 = 0; h2 < 2; h2++){
            int gr = rb*128 + warp_m*32 + mt*16 + h2*8 + qr;
            if (gr >= cnt) continue;
            size_t slot = (size_t)base + gr;
            #pragma unroll
            for (int nt = 0; nt < 4; nt++){
                float g0 = ag[mt][nt][h2*2+0], g1 = ag[mt][nt][h2*2+1];
                float u0 = au[mt][nt][h2*2+0], u1 = au[mt][nt][h2*2+1];
                float h0 = (g0 / (1.f + __expf(-g0))) * u0;
                float h1 = (g1 / (1.f + __expf(-g1))) * u1;
                __half2 vh; vh.x = __float2half(h0); vh.y = __float2half(h1);
                size_t col = (size_t)n0 + warp_n*32 + nt*8 + qc;
                *(__half2*)(g_hh + slot*I_DIM + col) = vh;
            }
        }
}

// ---------------- down-projection fp16 kernel (single product, 3-stage) ----------------
// CTA 128x128, 512 thr. Stage tiles: H@0 D@16K.
__global__ void __launch_bounds__(512) down_proj_kernel(){
    int z = blockIdx.z, cnt, base;
    if (z == E_EXP){ cnt = N_TOK; base = 2*N_TOK; }
    else           { cnt = g_counts[z]; base = g_offsets[z]; }
    int rb = blockIdx.y;
    if (rb*128 >= cnt) return;
    int n0 = blockIdx.x * 128;

    extern __shared__ char smem[];
    uint32_t sb = (smem_u32(smem) + 1023u) & ~1023u;
    int tid = threadIdx.x, lane = tid & 31, wid = tid >> 5;
    int warp_m = wid >> 2, warp_n = wid & 3;

    // loader: 2 tiles x 128 rows = 256 rows; threads 256..511 idle
    int ltile = tid >> 7, lrow = tid & 127;
    bool lval = tid < 256;
    const char* lsrc = (const char*)g_hh;
    if (lval){
        if (ltile == 0){
            int r = rb*128 + lrow; int rr = r < cnt ? r : cnt - 1;
            lsrc = (const char*)(g_hh + (size_t)(base + rr)*I_DIM);
        } else {
            size_t wr = ((size_t)z*C_DIM + n0 + lrow)*I_DIM;
            lsrc = (const char*)(g_wd + wr);
        }
    }
    uint32_t ltoff = (uint32_t)ltile*TILE_B;
    auto load_stage = [&](int s, int kt){
        uint32_t st = sb + (uint32_t)s*STAGE_D;
        if (lval) cp_row(st + ltoff, lsrc + kt*128, lrow);
        cp_commit();
    };

    int mat = lane >> 3;
    uint32_t xm = (uint32_t)(lane & 7) << 4;
    uint32_t rA[2], rB[2];
    #pragma unroll
    for (int mt = 0; mt < 2; mt++)
        rA[mt] = (uint32_t)(warp_m*32 + mt*16 + (mat & 1)*8 + (lane & 7)) << 7;
    #pragma unroll
    for (int p = 0; p < 2; p++)
        rB[p] = (uint32_t)(warp_n*32 + p*16 + ((mat >> 1) & 1)*8 + (lane & 7)) << 7;
    uint32_t caK = (uint32_t)((mat >> 1) & 1) * 16;
    uint32_t cbK = (uint32_t)(mat & 1) * 16;

    float ac[2][4][4];
    #pragma unroll
    for (int a = 0; a < 2; a++)
        #pragma unroll
        for (int b = 0; b < 4; b++)
            #pragma unroll
            for (int c = 0; c < 4; c++) ac[a][b][c] = 0.f;

    const int KT = I_DIM/64;   // 24
    load_stage(0, 0);
    load_stage(1, 1);

    for (int kt = 0; kt < KT; kt++){
        if (kt + 1 < KT) cp_wait1(); else cp_wait0();
        __syncthreads();
        if (kt + 2 < KT) load_stage((kt + 2) % 3, kt + 2);
        uint32_t st = sb + (uint32_t)(kt % 3)*STAGE_D;
        uint32_t Ht = st, Dt = st + TILE_B;
        #pragma unroll
        for (int ks = 0; ks < 4; ks++){
            uint32_t cA = ((uint32_t)ks*32 + caK) ^ xm;
            uint32_t cB = ((uint32_t)ks*32 + cbK) ^ xm;
            uint32_t ah[2][4];
            ldsm4(ah[0], Ht + rA[0] + cA); ldsm4(ah[1], Ht + rA[1] + cA);
            uint32_t bd[2][4];
            ldsm4(bd[0], Dt + rB[0] + cB); ldsm4(bd[1], Dt + rB[1] + cB);
            #pragma unroll
            for (int mt = 0; mt < 2; mt++)
                #pragma unroll
                for (int nt = 0; nt < 4; nt++)
                    hmma(ac[mt][nt], ah[mt], &bd[nt>>1][(nt&1)*2]);
        }
    }

    int qr = lane >> 2, qc = (lane & 3)*2;
    #pragma unroll
    for (int mt = 0; mt < 2; mt++)
        #pragma unroll
        for (int h2 = 0; h2 < 2; h2++){
            int gr = rb*128 + warp_m*32 + mt*16 + h2*8 + qr;
            if (gr >= cnt) continue;
            size_t slot = (size_t)base + gr;
            float wt = g_wt[slot];
            #pragma unroll
            for (int nt = 0; nt < 4; nt++){
                float2 v;
                v.x = wt * ac[mt][nt][h2*2+0];
                v.y = wt * ac[mt][nt][h2*2+1];
                size_t col = (size_t)n0 + warp_n*32 + nt*8 + qc;
                *(float2*)(g_O + slot*C_DIM + col) = v;
            }
        }
}

__global__ void combine_kernel(float* __restrict__ out){
    int i = blockIdx.x * blockDim.x + threadIdx.x;
    if (i >= N_TOK*(C_DIM/4)) return;
    int t = i / (C_DIM/4), c = (i % (C_DIM/4)) * 4;
    int s0 = g_slot_of[t*2], s1 = g_slot_of[t*2+1];
    float4 a = *(const float4*)&g_O[(size_t)s0*C_DIM + c];
    float4 b = *(const float4*)&g_O[(size_t)s1*C_DIM + c];
    float4 d = *(const float4*)&g_O[(size_t)(2*N_TOK + t)*C_DIM + c];
    float4 r = make_float4(a.x+b.x+d.x, a.y+b.y+d.y, a.z+b.z+d.z, a.w+b.w+d.w);
    *(float4*)&out[(size_t)t*C_DIM + c] = r;
}

// ---------------- launch ----------------
extern "C" void kernel_launch(void* const* d_in, const int* in_sizes, int n_in,
                              void* d_out, int out_size) {
    const float* x    = (const float*)d_in[0];
    const float* wgt  = (const float*)d_in[1];
    const float* bias = (const float*)d_in[2];
    const float* wg   = (const float*)d_in[3];
    const float* wu   = (const float*)d_in[4];
    const float* wd   = (const float*)d_in[5];
    const float* swg  = (const float*)d_in[6];
    const float* swu  = (const float*)d_in[7];
    const float* swd  = (const float*)d_in[8];
    float* out = (float*)d_out;

    cudaFuncSetAttribute(fused_gateup_kernel, cudaFuncAttributeMaxDynamicSharedMemorySize, SMEM_F);
    cudaFuncSetAttribute(down_proj_kernel,    cudaFuncAttributeMaxDynamicSharedMemorySize, SMEM_D);

    router_kernel<<<(N_TOK*32 + 255)/256, 256>>>(x, wgt, bias);   // #1
    scan2_kernel<<<1, 256>>>();                                   // #2
    fill_kernel<<<(N_TOK + 255)/256, 256>>>();                    // #3
    conv_x_kernel<<<(N_TOK*C_DIM + 255)/256, 256>>>(x);           // #4
    convT_all_kernel<<<dim3(48, 24, 3*E_ALL), dim3(32, 8)>>>(wg, swg, wu, swu, wd, swd); // #5
    fused_gateup_kernel<<<dim3(I_DIM/128, N_TOK/128, E_ALL), 512, SMEM_F>>>();  // #6 (ncu target)
    down_proj_kernel  <<<dim3(C_DIM/128, N_TOK/128, E_ALL), 512, SMEM_D>>>();   // #7
    combine_kernel<<<(N_TOK*(C_DIM/4) + 255)/256, 256>>>(out);    // #8
}